// round 1
// baseline (speedup 1.0000x reference)
#include <cuda_runtime.h>
#include <math.h>

#define TOKENS (4*8192)
#define DIM 1024
#define HMID 512
#define HLOW 256

// Scratch: device globals (no allocation in kernel_launch, per harness rules)
__device__ float g_ln[(size_t)TOKENS * DIM];   // 128 MB
__device__ float g_h1[(size_t)TOKENS * HMID];  //  64 MB
__device__ float g_h2[(size_t)TOKENS * HMID];  //  64 MB
__device__ float g_h3[(size_t)TOKENS * HLOW];  //  32 MB

// ---------------------------------------------------------------------------
// LayerNorm: one block per row of 1024 floats, 256 threads, 1 float4/thread.
// ---------------------------------------------------------------------------
__global__ __launch_bounds__(256) void ln_kernel(
    const float* __restrict__ x,
    const float* __restrict__ gamma,
    const float* __restrict__ beta,
    float* __restrict__ y)
{
    const int row = blockIdx.x;
    const int t = threadIdx.x;

    float4 v = reinterpret_cast<const float4*>(x + (size_t)row * DIM)[t];
    float s = v.x + v.y + v.z + v.w;
    float q = v.x*v.x + v.y*v.y + v.z*v.z + v.w*v.w;

    #pragma unroll
    for (int o = 16; o > 0; o >>= 1) {
        s += __shfl_xor_sync(0xffffffffu, s, o);
        q += __shfl_xor_sync(0xffffffffu, q, o);
    }

    __shared__ float sh_s[8], sh_q[8];
    const int w = t >> 5, l = t & 31;
    if (l == 0) { sh_s[w] = s; sh_q[w] = q; }
    __syncthreads();
    if (t < 32) {
        s = (t < 8) ? sh_s[t] : 0.0f;
        q = (t < 8) ? sh_q[t] : 0.0f;
        #pragma unroll
        for (int o = 4; o > 0; o >>= 1) {
            s += __shfl_xor_sync(0xffffffffu, s, o);
            q += __shfl_xor_sync(0xffffffffu, q, o);
        }
        if (t == 0) { sh_s[0] = s; sh_q[0] = q; }
    }
    __syncthreads();
    s = sh_s[0]; q = sh_q[0];

    const float mu  = s * (1.0f / DIM);
    const float var = q * (1.0f / DIM) - mu * mu;
    const float rs  = rsqrtf(var + 1e-5f);

    float4 g = reinterpret_cast<const float4*>(gamma)[t];
    float4 b = reinterpret_cast<const float4*>(beta)[t];
    float4 o;
    o.x = (v.x - mu) * rs * g.x + b.x;
    o.y = (v.y - mu) * rs * g.y + b.y;
    o.z = (v.z - mu) * rs * g.z + b.z;
    o.w = (v.w - mu) * rs * g.w + b.w;
    reinterpret_cast<float4*>(y + (size_t)row * DIM)[t] = o;
}

__device__ __forceinline__ float gelu_exact(float v) {
    // torch-default exact GELU: 0.5*x*(1+erf(x/sqrt(2)))
    return 0.5f * v * (1.0f + erff(v * 0.70710678118654752f));
}

// ---------------------------------------------------------------------------
// Tiled fp32 GEMM: C[M,N] = epilogue(A[M,K] @ B[K,N] + bias [+ res])
// BM=BN=128, BK=16, 256 threads, 8x8 per-thread tile split as (4+4)x(4+4)
// so all shared loads are conflict-free/broadcast LDS.128.
// All problem dims divide the tile sizes exactly (M=32768; N,K in
// {256,512,1024}); no bounds checks needed.
// ---------------------------------------------------------------------------
template<bool DO_GELU, bool DO_RES>
__global__ __launch_bounds__(256, 2) void gemm_kernel(
    const float* __restrict__ A, const float* __restrict__ B,
    const float* __restrict__ bias, const float* __restrict__ res,
    float* __restrict__ C, int M, int N, int K)
{
    constexpr int BM = 128, BN = 128, BK = 16;
    __shared__ float As[BK][BM + 4];   // +4 pad: de-conflicts transposed STS
    __shared__ float Bs[BK][BN];

    const int tid = threadIdx.x;
    const int tx = tid & 15;           // N direction (16 lanes)
    const int ty = tid >> 4;           // M direction (16 rows)
    const int m0 = blockIdx.y * BM;
    const int n0 = blockIdx.x * BN;

    float acc[8][8];
    #pragma unroll
    for (int i = 0; i < 8; i++)
        #pragma unroll
        for (int j = 0; j < 8; j++) acc[i][j] = 0.0f;

    const float* Ag = A + (size_t)m0 * K;
    const float* Bg = B + n0;

    for (int k0 = 0; k0 < K; k0 += BK) {
        // A tile: 128 rows x 16 k -> transposed into As[k][m]
        #pragma unroll
        for (int jj = 0; jj < 2; jj++) {
            int idx = tid + jj * 256;          // 512 float4 total
            int row = idx >> 2;
            int kq  = (idx & 3) * 4;
            float4 v = *reinterpret_cast<const float4*>(
                Ag + (size_t)row * K + (k0 + kq));
            As[kq + 0][row] = v.x;
            As[kq + 1][row] = v.y;
            As[kq + 2][row] = v.z;
            As[kq + 3][row] = v.w;
        }
        // B tile: 16 k x 128 n, direct
        #pragma unroll
        for (int jj = 0; jj < 2; jj++) {
            int idx = tid + jj * 256;
            int row = idx >> 5;
            int c   = (idx & 31) * 4;
            float4 v = *reinterpret_cast<const float4*>(
                Bg + (size_t)(k0 + row) * N + c);
            *reinterpret_cast<float4*>(&Bs[row][c]) = v;
        }
        __syncthreads();

        #pragma unroll
        for (int kk = 0; kk < BK; kk++) {
            float a[8], b[8];
            *reinterpret_cast<float4*>(&a[0]) =
                *reinterpret_cast<const float4*>(&As[kk][ty * 4]);
            *reinterpret_cast<float4*>(&a[4]) =
                *reinterpret_cast<const float4*>(&As[kk][64 + ty * 4]);
            *reinterpret_cast<float4*>(&b[0]) =
                *reinterpret_cast<const float4*>(&Bs[kk][tx * 4]);
            *reinterpret_cast<float4*>(&b[4]) =
                *reinterpret_cast<const float4*>(&Bs[kk][64 + tx * 4]);
            #pragma unroll
            for (int i = 0; i < 8; i++)
                #pragma unroll
                for (int j = 0; j < 8; j++)
                    acc[i][j] = fmaf(a[i], b[j], acc[i][j]);
        }
        __syncthreads();
    }

    // Epilogue: bias (+ GELU) (+ residual), vectorized float4 stores
    float bv[8];
    *reinterpret_cast<float4*>(&bv[0]) =
        *reinterpret_cast<const float4*>(bias + n0 + tx * 4);
    *reinterpret_cast<float4*>(&bv[4]) =
        *reinterpret_cast<const float4*>(bias + n0 + 64 + tx * 4);

    #pragma unroll
    for (int i = 0; i < 8; i++) {
        const int gm = m0 + ((i < 4) ? (ty * 4 + i) : (64 + ty * 4 + (i - 4)));
        #pragma unroll
        for (int h = 0; h < 2; h++) {
            const int gn = n0 + h * 64 + tx * 4;
            float4 o;
            float* po = &o.x;
            #pragma unroll
            for (int j = 0; j < 4; j++) {
                float v = acc[i][h * 4 + j] + bv[h * 4 + j];
                if (DO_GELU) v = gelu_exact(v);
                po[j] = v;
            }
            if (DO_RES) {
                float4 r = *reinterpret_cast<const float4*>(
                    res + (size_t)gm * N + gn);
                o.x += r.x; o.y += r.y; o.z += r.z; o.w += r.w;
            }
            *reinterpret_cast<float4*>(C + (size_t)gm * N + gn) = o;
        }
    }
}

// ---------------------------------------------------------------------------
// Launch: LN -> G1(gelu) -> G2(gelu) -> G3(gelu) -> G4(+bias, +x residual)
// Input order (metadata): x, gamma, beta, W1,b1, W2,b2, W3,b3, W4,b4
// ---------------------------------------------------------------------------
extern "C" void kernel_launch(void* const* d_in, const int* in_sizes, int n_in,
                              void* d_out, int out_size)
{
    const float* x     = (const float*)d_in[0];
    const float* gamma = (const float*)d_in[1];
    const float* beta  = (const float*)d_in[2];
    const float* W1    = (const float*)d_in[3];
    const float* b1    = (const float*)d_in[4];
    const float* W2    = (const float*)d_in[5];
    const float* b2    = (const float*)d_in[6];
    const float* W3    = (const float*)d_in[7];
    const float* b3    = (const float*)d_in[8];
    const float* W4    = (const float*)d_in[9];
    const float* b4    = (const float*)d_in[10];
    float* out = (float*)d_out;

    float *p_ln, *p_h1, *p_h2, *p_h3;
    cudaGetSymbolAddress((void**)&p_ln, g_ln);
    cudaGetSymbolAddress((void**)&p_h1, g_h1);
    cudaGetSymbolAddress((void**)&p_h2, g_h2);
    cudaGetSymbolAddress((void**)&p_h3, g_h3);

    ln_kernel<<<TOKENS, 256>>>(x, gamma, beta, p_ln);

    gemm_kernel<true, false><<<dim3(HMID / 128, TOKENS / 128), 256>>>(
        p_ln, W1, b1, nullptr, p_h1, TOKENS, HMID, DIM);
    gemm_kernel<true, false><<<dim3(HMID / 128, TOKENS / 128), 256>>>(
        p_h1, W2, b2, nullptr, p_h2, TOKENS, HMID, HMID);
    gemm_kernel<true, false><<<dim3(HLOW / 128, TOKENS / 128), 256>>>(
        p_h2, W3, b3, nullptr, p_h3, TOKENS, HLOW, HMID);
    gemm_kernel<false, true><<<dim3(DIM / 128, TOKENS / 128), 256>>>(
        p_h3, W4, b4, x, out, TOKENS, DIM, HLOW);
}

// round 4
// speedup vs baseline: 4.6801x; 4.6801x over previous
#include <cuda_runtime.h>
#include <cuda_fp16.h>
#include <math.h>
#include <cstdint>

#define TOKENS (4*8192)
#define DIM 1024
#define HMID 512
#define HLOW 256

// ---------------------------------------------------------------------------
// Scratch (device globals; no allocation anywhere)
// ---------------------------------------------------------------------------
__device__ __half g_ln[(size_t)TOKENS * DIM];   // 64 MB
__device__ __half g_h1[(size_t)TOKENS * HMID];  // 32 MB
__device__ __half g_h2[(size_t)TOKENS * HMID];  // 32 MB
__device__ __half g_h3[(size_t)TOKENS * HLOW];  // 16 MB
// Transposed fp16 weights: Wt[n*K + k]
__device__ __half g_w1[(size_t)HMID * DIM];
__device__ __half g_w2[(size_t)HMID * HMID];
__device__ __half g_w3[(size_t)HLOW * HMID];
__device__ __half g_w4[(size_t)DIM * HLOW];

// ---------------------------------------------------------------------------
// Helpers (all base-target PTX: sm_80-era features only)
// ---------------------------------------------------------------------------
__device__ __forceinline__ uint32_t smem_u32(const void* p) {
    uint32_t a;
    asm("{ .reg .u64 t; cvta.to.shared.u64 t, %1; cvt.u32.u64 %0, t; }"
        : "=r"(a) : "l"(p));
    return a;
}
#define SW128(bo) ((bo) ^ (((bo) >> 3) & 0x70))

#define CP_ASYNC16(dst, src) \
    asm volatile("cp.async.cg.shared.global [%0], [%1], 16;" \
                 :: "r"(dst), "l"(src))
#define CP_COMMIT() asm volatile("cp.async.commit_group;" ::: "memory")
#define CP_WAIT(n)  asm volatile("cp.async.wait_group %0;" :: "n"(n) : "memory")

#define LDMATRIX_X4(r0, r1, r2, r3, a) \
    asm volatile("ldmatrix.sync.aligned.m8n8.x4.shared.b16 {%0,%1,%2,%3}, [%4];" \
                 : "=r"(r0), "=r"(r1), "=r"(r2), "=r"(r3) : "r"(a))

#define MMA16816(c0, c1, c2, c3, a0, a1, a2, a3, b0, b1) \
    asm volatile("mma.sync.aligned.m16n8k16.row.col.f32.f16.f16.f32 " \
                 "{%0,%1,%2,%3}, {%4,%5,%6,%7}, {%8,%9}, {%0,%1,%2,%3};" \
                 : "+f"(c0), "+f"(c1), "+f"(c2), "+f"(c3) \
                 : "r"(a0), "r"(a1), "r"(a2), "r"(a3), "r"(b0), "r"(b1))

__device__ __forceinline__ float gelu_exact(float v) {
    return 0.5f * v * (1.0f + erff(v * 0.70710678118654752f));
}

// ---------------------------------------------------------------------------
// Weight prep: W[K,N] fp32 -> Wt[N,K] fp16
// ---------------------------------------------------------------------------
__global__ void wprep_kernel(const float* __restrict__ W, int K, int N,
                             __half* __restrict__ T) {
    int idx = blockIdx.x * blockDim.x + threadIdx.x;
    if (idx >= N * K) return;
    int n = idx / K, k = idx - n * K;
    T[idx] = __float2half_rn(W[(size_t)k * N + n]);
}

// ---------------------------------------------------------------------------
// LayerNorm -> fp16 output
// ---------------------------------------------------------------------------
__global__ __launch_bounds__(256) void ln_kernel(
    const float* __restrict__ x, const float* __restrict__ gamma,
    const float* __restrict__ beta, __half* __restrict__ y)
{
    const int row = blockIdx.x, t = threadIdx.x;
    float4 v = reinterpret_cast<const float4*>(x + (size_t)row * DIM)[t];
    float s = v.x + v.y + v.z + v.w;
    float q = v.x*v.x + v.y*v.y + v.z*v.z + v.w*v.w;
    #pragma unroll
    for (int o = 16; o > 0; o >>= 1) {
        s += __shfl_xor_sync(~0u, s, o);
        q += __shfl_xor_sync(~0u, q, o);
    }
    __shared__ float ss[8], sq[8];
    int w = t >> 5, l = t & 31;
    if (l == 0) { ss[w] = s; sq[w] = q; }
    __syncthreads();
    if (t < 32) {
        s = (t < 8) ? ss[t] : 0.0f; q = (t < 8) ? sq[t] : 0.0f;
        #pragma unroll
        for (int o = 4; o > 0; o >>= 1) {
            s += __shfl_xor_sync(~0u, s, o);
            q += __shfl_xor_sync(~0u, q, o);
        }
        if (t == 0) { ss[0] = s; sq[0] = q; }
    }
    __syncthreads();
    s = ss[0]; q = sq[0];
    float mu = s * (1.0f / DIM);
    float var = q * (1.0f / DIM) - mu * mu;
    float rs = rsqrtf(var + 1e-5f);

    float4 g = reinterpret_cast<const float4*>(gamma)[t];
    float4 b = reinterpret_cast<const float4*>(beta)[t];
    __half2 h0 = __halves2half2(__float2half_rn((v.x-mu)*rs*g.x + b.x),
                                __float2half_rn((v.y-mu)*rs*g.y + b.y));
    __half2 h1 = __halves2half2(__float2half_rn((v.z-mu)*rs*g.z + b.z),
                                __float2half_rn((v.w-mu)*rs*g.w + b.w));
    uint2 pack = { *reinterpret_cast<uint32_t*>(&h0), *reinterpret_cast<uint32_t*>(&h1) };
    *reinterpret_cast<uint2*>(y + (size_t)row * DIM + t * 4) = pack;
}

// ---------------------------------------------------------------------------
// fp16 tensor-core GEMM: C[128x128 tile] = A[M,K] @ Wt[N,K]^T
// 8 warps (4x2), warp tile 32x64, BK=64, cp.async double buffer, SW128 smem.
// MODE 0: Oh = fp16(gelu(acc+bias));  MODE 1: Of = acc+bias+res (fp32)
// ---------------------------------------------------------------------------
#define STAGE_BYTES 32768          // A 16KB + B 16KB per stage
#define SMEM_TOTAL  (2 * STAGE_BYTES)

template<int MODE>
__global__ __launch_bounds__(256, 2) void hgemm(
    const __half* __restrict__ A, const __half* __restrict__ Bw,
    const float* __restrict__ bias, const float* __restrict__ res,
    __half* __restrict__ Oh, float* __restrict__ Of, int N, int K)
{
    extern __shared__ char smem[];
    const uint32_t sb = smem_u32(smem);
    const int tid = threadIdx.x, lid = tid & 31, wid = tid >> 5;
    const int m0 = blockIdx.y * 128, n0 = blockIdx.x * 128;
    const int wm = (wid & 3) * 32;       // warp M offset
    const int wn = (wid >> 2) * 64;      // warp N offset
    const int nch = K >> 6;

    float acc[2][8][4];
    #pragma unroll
    for (int i = 0; i < 2; i++)
        #pragma unroll
        for (int j = 0; j < 8; j++)
            #pragma unroll
            for (int k = 0; k < 4; k++) acc[i][j][k] = 0.0f;

    // --- stage loader: 128 rows x 64 fp16 for A and B, SW128 swizzled ---
    auto load_stage = [&](int s, int c) {
        const int k0 = c << 6;
        #pragma unroll
        for (int i = 0; i < 4; i++) {
            int idx = tid + i * 256;           // 1024 chunks of 16B (A)
            int r = idx >> 3, ch = idx & 7;
            uint32_t d = sb + s * STAGE_BYTES + SW128((uint32_t)(r * 128 + ch * 16));
            CP_ASYNC16(d, A + (size_t)(m0 + r) * K + k0 + ch * 8);
        }
        #pragma unroll
        for (int i = 0; i < 4; i++) {
            int idx = tid + i * 256;
            int r = idx >> 3, ch = idx & 7;
            uint32_t d = sb + s * STAGE_BYTES + 16384 + SW128((uint32_t)(r * 128 + ch * 16));
            CP_ASYNC16(d, Bw + (size_t)(n0 + r) * K + k0 + ch * 8);
        }
        CP_COMMIT();
    };

    load_stage(0, 0);
    load_stage(1, 1);

    // ldmatrix lane address components (fixed per thread)
    const int lrow = (lid & 7) + ((lid >> 3) & 1) * 8;   // row within 16
    const int lkb  = (lid >> 4) * 16;                    // 0 or 16 bytes (k half)

    for (int c = 0; c < nch; ++c) {
        if (c < nch - 1) { CP_WAIT(1); } else { CP_WAIT(0); }
        __syncthreads();
        const int s = c & 1;
        const uint32_t abase = sb + s * STAGE_BYTES;
        const uint32_t bbase = abase + 16384;

        #pragma unroll
        for (int kk = 0; kk < 4; ++kk) {
            uint32_t a[2][4], b[8][2];
            #pragma unroll
            for (int mt = 0; mt < 2; ++mt) {
                uint32_t bo = (uint32_t)((wm + mt * 16 + lrow) * 128 + kk * 32 + lkb);
                LDMATRIX_X4(a[mt][0], a[mt][1], a[mt][2], a[mt][3], abase + SW128(bo));
            }
            #pragma unroll
            for (int jp = 0; jp < 4; ++jp) {       // pairs of n8 tiles
                uint32_t r0, r1, r2, r3;
                uint32_t bo = (uint32_t)((wn + jp * 16 + lrow) * 128 + kk * 32 + lkb);
                LDMATRIX_X4(r0, r1, r2, r3, bbase + SW128(bo));
                b[jp * 2][0] = r0; b[jp * 2 + 1][0] = r1;
                b[jp * 2][1] = r2; b[jp * 2 + 1][1] = r3;
            }
            #pragma unroll
            for (int mt = 0; mt < 2; ++mt)
                #pragma unroll
                for (int nt = 0; nt < 8; ++nt)
                    MMA16816(acc[mt][nt][0], acc[mt][nt][1],
                             acc[mt][nt][2], acc[mt][nt][3],
                             a[mt][0], a[mt][1], a[mt][2], a[mt][3],
                             b[nt][0], b[nt][1]);
        }
        __syncthreads();
        if (c + 2 < nch) load_stage(s, c + 2);
    }

    // --- epilogue ---
    const int mrow = m0 + wm + (lid >> 2);
    const int ncb  = n0 + wn + (lid & 3) * 2;
    #pragma unroll
    for (int mt = 0; mt < 2; ++mt) {
        const int r0 = mrow + mt * 16;
        #pragma unroll
        for (int nt = 0; nt < 8; ++nt) {
            const int n = ncb + nt * 8;
            float2 bv = *reinterpret_cast<const float2*>(bias + n);
            if (MODE == 0) {
                float v0 = gelu_exact(acc[mt][nt][0] + bv.x);
                float v1 = gelu_exact(acc[mt][nt][1] + bv.y);
                float v2 = gelu_exact(acc[mt][nt][2] + bv.x);
                float v3 = gelu_exact(acc[mt][nt][3] + bv.y);
                __half2 p0 = __halves2half2(__float2half_rn(v0), __float2half_rn(v1));
                __half2 p1 = __halves2half2(__float2half_rn(v2), __float2half_rn(v3));
                *reinterpret_cast<__half2*>(Oh + (size_t)r0 * N + n) = p0;
                *reinterpret_cast<__half2*>(Oh + (size_t)(r0 + 8) * N + n) = p1;
            } else {
                float2 ra = *reinterpret_cast<const float2*>(res + (size_t)r0 * N + n);
                float2 rb = *reinterpret_cast<const float2*>(res + (size_t)(r0 + 8) * N + n);
                float2 o0 = { acc[mt][nt][0] + bv.x + ra.x, acc[mt][nt][1] + bv.y + ra.y };
                float2 o1 = { acc[mt][nt][2] + bv.x + rb.x, acc[mt][nt][3] + bv.y + rb.y };
                *reinterpret_cast<float2*>(Of + (size_t)r0 * N + n) = o0;
                *reinterpret_cast<float2*>(Of + (size_t)(r0 + 8) * N + n) = o1;
            }
        }
    }
}

// ---------------------------------------------------------------------------
extern "C" void kernel_launch(void* const* d_in, const int* in_sizes, int n_in,
                              void* d_out, int out_size)
{
    const float* x     = (const float*)d_in[0];
    const float* gamma = (const float*)d_in[1];
    const float* beta  = (const float*)d_in[2];
    const float* W1 = (const float*)d_in[3];  const float* b1 = (const float*)d_in[4];
    const float* W2 = (const float*)d_in[5];  const float* b2 = (const float*)d_in[6];
    const float* W3 = (const float*)d_in[7];  const float* b3 = (const float*)d_in[8];
    const float* W4 = (const float*)d_in[9];  const float* b4 = (const float*)d_in[10];
    float* out = (float*)d_out;

    __half *ln, *h1, *h2, *h3, *w1, *w2, *w3, *w4;
    cudaGetSymbolAddress((void**)&ln, g_ln);
    cudaGetSymbolAddress((void**)&h1, g_h1);
    cudaGetSymbolAddress((void**)&h2, g_h2);
    cudaGetSymbolAddress((void**)&h3, g_h3);
    cudaGetSymbolAddress((void**)&w1, g_w1);
    cudaGetSymbolAddress((void**)&w2, g_w2);
    cudaGetSymbolAddress((void**)&w3, g_w3);
    cudaGetSymbolAddress((void**)&w4, g_w4);

    cudaFuncSetAttribute(hgemm<0>, cudaFuncAttributeMaxDynamicSharedMemorySize, SMEM_TOTAL);
    cudaFuncSetAttribute(hgemm<1>, cudaFuncAttributeMaxDynamicSharedMemorySize, SMEM_TOTAL);

    wprep_kernel<<<(HMID * DIM + 255) / 256, 256>>>(W1, DIM,  HMID, w1);
    wprep_kernel<<<(HMID * HMID + 255) / 256, 256>>>(W2, HMID, HMID, w2);
    wprep_kernel<<<(HLOW * HMID + 255) / 256, 256>>>(W3, HMID, HLOW, w3);
    wprep_kernel<<<(DIM * HLOW + 255) / 256, 256>>>(W4, HLOW, DIM,  w4);

    ln_kernel<<<TOKENS, 256>>>(x, gamma, beta, ln);

    hgemm<0><<<dim3(HMID / 128, TOKENS / 128), 256, SMEM_TOTAL>>>(
        ln, w1, b1, nullptr, h1, nullptr, HMID, DIM);
    hgemm<0><<<dim3(HMID / 128, TOKENS / 128), 256, SMEM_TOTAL>>>(
        h1, w2, b2, nullptr, h2, nullptr, HMID, HMID);
    hgemm<0><<<dim3(HLOW / 128, TOKENS / 128), 256, SMEM_TOTAL>>>(
        h2, w3, b3, nullptr, h3, nullptr, HLOW, HMID);
    hgemm<1><<<dim3(DIM / 128, TOKENS / 128), 256, SMEM_TOTAL>>>(
        h3, w4, b4, x, nullptr, out, DIM, HLOW);
}

// round 5
// speedup vs baseline: 4.7244x; 1.0095x over previous
#include <cuda_runtime.h>
#include <cuda_fp16.h>
#include <math.h>
#include <cstdint>

#define TOKENS (4*8192)
#define DIM 1024
#define HMID 512
#define HLOW 256

// ---------------------------------------------------------------------------
// Scratch (device globals; no allocation anywhere)
// ---------------------------------------------------------------------------
__device__ __half g_ln[(size_t)TOKENS * DIM];   // 64 MB
__device__ __half g_h1[(size_t)TOKENS * HMID];  // 32 MB
__device__ __half g_h2[(size_t)TOKENS * HMID];  // 32 MB
__device__ __half g_h3[(size_t)TOKENS * HLOW];  // 16 MB
// Transposed fp16 weights: Wt[n*K + k]
__device__ __half g_w1[(size_t)HMID * DIM];
__device__ __half g_w2[(size_t)HMID * HMID];
__device__ __half g_w3[(size_t)HLOW * HMID];
__device__ __half g_w4[(size_t)DIM * HLOW];

// ---------------------------------------------------------------------------
// Helpers (base-target PTX only: sm_80-era features)
// ---------------------------------------------------------------------------
__device__ __forceinline__ uint32_t smem_u32(const void* p) {
    uint32_t a;
    asm("{ .reg .u64 t; cvta.to.shared.u64 t, %1; cvt.u32.u64 %0, t; }"
        : "=r"(a) : "l"(p));
    return a;
}
#define SW128(bo) ((bo) ^ (((bo) >> 3) & 0x70))

#define CP_ASYNC16(dst, src) \
    asm volatile("cp.async.cg.shared.global [%0], [%1], 16;" \
                 :: "r"(dst), "l"(src))
#define CP_COMMIT() asm volatile("cp.async.commit_group;" ::: "memory")
#define CP_WAIT(n)  asm volatile("cp.async.wait_group %0;" :: "n"(n) : "memory")

#define LDMATRIX_X4(r0, r1, r2, r3, a) \
    asm volatile("ldmatrix.sync.aligned.m8n8.x4.shared.b16 {%0,%1,%2,%3}, [%4];" \
                 : "=r"(r0), "=r"(r1), "=r"(r2), "=r"(r3) : "r"(a))

#define MMA16816(c0, c1, c2, c3, a0, a1, a2, a3, b0, b1) \
    asm volatile("mma.sync.aligned.m16n8k16.row.col.f32.f16.f16.f32 " \
                 "{%0,%1,%2,%3}, {%4,%5,%6,%7}, {%8,%9}, {%0,%1,%2,%3};" \
                 : "+f"(c0), "+f"(c1), "+f"(c2), "+f"(c3) \
                 : "r"(a0), "r"(a1), "r"(a2), "r"(a3), "r"(b0), "r"(b1))

__device__ __forceinline__ float gelu_exact(float v) {
    return 0.5f * v * (1.0f + erff(v * 0.70710678118654752f));
}

// ---------------------------------------------------------------------------
// Fused weight prep: all 4 weights, W[K,N] fp32 -> Wt[N,K] fp16, one launch
// ---------------------------------------------------------------------------
__global__ void wprep_all(const float* __restrict__ W1, const float* __restrict__ W2,
                          const float* __restrict__ W3, const float* __restrict__ W4,
                          __half* __restrict__ T1, __half* __restrict__ T2,
                          __half* __restrict__ T3, __half* __restrict__ T4)
{
    // element counts: W1 512K, W2 256K, W3 128K, W4 256K  (total 1152K)
    int idx = blockIdx.x * blockDim.x + threadIdx.x;
    const float* W; __half* T; int K; int base;
    if (idx < 524288)        { W = W1; T = T1; K = DIM;  base = 0;        }
    else if (idx < 786432)   { W = W2; T = T2; K = HMID; base = 524288;   }
    else if (idx < 917504)   { W = W3; T = T3; K = HMID; base = 786432;   }
    else if (idx < 1179648)  { W = W4; T = T4; K = HLOW; base = 917504;   }
    else return;
    int i = idx - base;
    int n = i / K, k = i - n * K;
    // N = total/K
    int N = (idx < 524288) ? HMID : (idx < 786432) ? HMID : (idx < 917504) ? HLOW : DIM;
    T[i] = __float2half_rn(W[(size_t)k * N + n]);
}

// ---------------------------------------------------------------------------
// LayerNorm, warp-per-row (no smem, no block barrier): 8 rows / 256-thr block
// ---------------------------------------------------------------------------
__global__ __launch_bounds__(256) void ln_kernel(
    const float* __restrict__ x, const float* __restrict__ gamma,
    const float* __restrict__ beta, __half* __restrict__ y)
{
    const int warp = threadIdx.x >> 5, lane = threadIdx.x & 31;
    const int row = blockIdx.x * 8 + warp;
    const float* xr = x + (size_t)row * DIM;

    float4 v[8];
    float s = 0.0f, q = 0.0f;
    #pragma unroll
    for (int j = 0; j < 8; j++) {
        v[j] = reinterpret_cast<const float4*>(xr)[j * 32 + lane];
        s += v[j].x + v[j].y + v[j].z + v[j].w;
        q += v[j].x*v[j].x + v[j].y*v[j].y + v[j].z*v[j].z + v[j].w*v[j].w;
    }
    #pragma unroll
    for (int o = 16; o > 0; o >>= 1) {
        s += __shfl_xor_sync(~0u, s, o);
        q += __shfl_xor_sync(~0u, q, o);
    }
    const float mu = s * (1.0f / DIM);
    const float var = q * (1.0f / DIM) - mu * mu;
    const float rs = rsqrtf(var + 1e-5f);

    __half* yr = y + (size_t)row * DIM;
    #pragma unroll
    for (int j = 0; j < 8; j++) {
        float4 g = reinterpret_cast<const float4*>(gamma)[j * 32 + lane];
        float4 b = reinterpret_cast<const float4*>(beta)[j * 32 + lane];
        __half2 h0 = __halves2half2(__float2half_rn((v[j].x - mu) * rs * g.x + b.x),
                                    __float2half_rn((v[j].y - mu) * rs * g.y + b.y));
        __half2 h1 = __halves2half2(__float2half_rn((v[j].z - mu) * rs * g.z + b.z),
                                    __float2half_rn((v[j].w - mu) * rs * g.w + b.w));
        uint2 pack = { *reinterpret_cast<uint32_t*>(&h0), *reinterpret_cast<uint32_t*>(&h1) };
        *reinterpret_cast<uint2*>(yr + (size_t)(j * 32 + lane) * 4) = pack;
    }
}

// ---------------------------------------------------------------------------
// fp16 tensor-core GEMM: C[128x128 tile] = A[M,K] @ Wt[N,K]^T
// 8 warps (4x2), warp tile 32x64, BK=64, 3-stage cp.async, 1 sync/iter.
// MODE 0: Oh = fp16(gelu(acc+bias));  MODE 1: Of = acc+bias+res (fp32)
// ---------------------------------------------------------------------------
#define STAGE_BYTES 32768          // A 16KB + B 16KB per stage
#define NSTAGE 3
#define SMEM_TOTAL  (NSTAGE * STAGE_BYTES)

template<int MODE>
__global__ __launch_bounds__(256, 2) void hgemm(
    const __half* __restrict__ A, const __half* __restrict__ Bw,
    const float* __restrict__ bias, const float* __restrict__ res,
    __half* __restrict__ Oh, float* __restrict__ Of, int N, int K)
{
    extern __shared__ char smem[];
    const uint32_t sb = smem_u32(smem);
    const int tid = threadIdx.x, lid = tid & 31, wid = tid >> 5;
    const int m0 = blockIdx.y * 128, n0 = blockIdx.x * 128;
    const int wm = (wid & 3) * 32;       // warp M offset
    const int wn = (wid >> 2) * 64;      // warp N offset
    const int nch = K >> 6;              // K/64 >= 4 for all layers

    float acc[2][8][4];
    #pragma unroll
    for (int i = 0; i < 2; i++)
        #pragma unroll
        for (int j = 0; j < 8; j++)
            #pragma unroll
            for (int k = 0; k < 4; k++) acc[i][j][k] = 0.0f;

    // per-thread load coords (fixed)
    const int lr = tid >> 3, lch = tid & 7;   // used with +32-row strides

    auto load_stage = [&](int s, int c) {
        const int k0 = c << 6;
        const uint32_t base = sb + s * STAGE_BYTES;
        #pragma unroll
        for (int i = 0; i < 4; i++) {
            int r = lr + i * 32;
            uint32_t d = base + SW128((uint32_t)(r * 128 + lch * 16));
            CP_ASYNC16(d, A + (size_t)(m0 + r) * K + k0 + lch * 8);
        }
        #pragma unroll
        for (int i = 0; i < 4; i++) {
            int r = lr + i * 32;
            uint32_t d = base + 16384 + SW128((uint32_t)(r * 128 + lch * 16));
            CP_ASYNC16(d, Bw + (size_t)(n0 + r) * K + k0 + lch * 8);
        }
        CP_COMMIT();
    };

    // prologue: stages 0,1
    load_stage(0, 0);
    load_stage(1, 1);

    // ldmatrix lane address components
    const int lrow = (lid & 7) + ((lid >> 3) & 1) * 8;
    const int lkb  = (lid >> 4) * 16;

    for (int c = 0; c < nch; ++c) {
        CP_WAIT(1);                  // group c complete (c and c+1 pending)
        __syncthreads();             // also proves buffer (c-1)%3 fully consumed
        // prefetch c+2 into buffer (c+2)%3 == (c-1)%3 (safe after sync)
        if (c + 2 < nch) load_stage((c + 2) % NSTAGE, c + 2);
        else CP_COMMIT();            // empty group keeps CP_WAIT(1) semantics exact

        const uint32_t abase = sb + (c % NSTAGE) * STAGE_BYTES;
        const uint32_t bbase = abase + 16384;

        #pragma unroll
        for (int kk = 0; kk < 4; ++kk) {
            uint32_t a[2][4], b[8][2];
            #pragma unroll
            for (int mt = 0; mt < 2; ++mt) {
                uint32_t bo = (uint32_t)((wm + mt * 16 + lrow) * 128 + kk * 32 + lkb);
                LDMATRIX_X4(a[mt][0], a[mt][1], a[mt][2], a[mt][3], abase + SW128(bo));
            }
            #pragma unroll
            for (int jp = 0; jp < 4; ++jp) {
                uint32_t r0, r1, r2, r3;
                uint32_t bo = (uint32_t)((wn + jp * 16 + lrow) * 128 + kk * 32 + lkb);
                LDMATRIX_X4(r0, r1, r2, r3, bbase + SW128(bo));
                b[jp * 2][0] = r0; b[jp * 2 + 1][0] = r1;
                b[jp * 2][1] = r2; b[jp * 2 + 1][1] = r3;
            }
            #pragma unroll
            for (int mt = 0; mt < 2; ++mt)
                #pragma unroll
                for (int nt = 0; nt < 8; ++nt)
                    MMA16816(acc[mt][nt][0], acc[mt][nt][1],
                             acc[mt][nt][2], acc[mt][nt][3],
                             a[mt][0], a[mt][1], a[mt][2], a[mt][3],
                             b[nt][0], b[nt][1]);
        }
    }

    // --- epilogue ---
    const int mrow = m0 + wm + (lid >> 2);
    const int ncb  = n0 + wn + (lid & 3) * 2;
    #pragma unroll
    for (int mt = 0; mt < 2; ++mt) {
        const int r0 = mrow + mt * 16;
        #pragma unroll
        for (int nt = 0; nt < 8; ++nt) {
            const int n = ncb + nt * 8;
            float2 bv = *reinterpret_cast<const float2*>(bias + n);
            if (MODE == 0) {
                float v0 = gelu_exact(acc[mt][nt][0] + bv.x);
                float v1 = gelu_exact(acc[mt][nt][1] + bv.y);
                float v2 = gelu_exact(acc[mt][nt][2] + bv.x);
                float v3 = gelu_exact(acc[mt][nt][3] + bv.y);
                __half2 p0 = __halves2half2(__float2half_rn(v0), __float2half_rn(v1));
                __half2 p1 = __halves2half2(__float2half_rn(v2), __float2half_rn(v3));
                *reinterpret_cast<__half2*>(Oh + (size_t)r0 * N + n) = p0;
                *reinterpret_cast<__half2*>(Oh + (size_t)(r0 + 8) * N + n) = p1;
            } else {
                float2 ra = *reinterpret_cast<const float2*>(res + (size_t)r0 * N + n);
                float2 rb = *reinterpret_cast<const float2*>(res + (size_t)(r0 + 8) * N + n);
                float2 o0 = { acc[mt][nt][0] + bv.x + ra.x, acc[mt][nt][1] + bv.y + ra.y };
                float2 o1 = { acc[mt][nt][2] + bv.x + rb.x, acc[mt][nt][3] + bv.y + rb.y };
                *reinterpret_cast<float2*>(Of + (size_t)r0 * N + n) = o0;
                *reinterpret_cast<float2*>(Of + (size_t)(r0 + 8) * N + n) = o1;
            }
        }
    }
}

// ---------------------------------------------------------------------------
extern "C" void kernel_launch(void* const* d_in, const int* in_sizes, int n_in,
                              void* d_out, int out_size)
{
    const float* x     = (const float*)d_in[0];
    const float* gamma = (const float*)d_in[1];
    const float* beta  = (const float*)d_in[2];
    const float* W1 = (const float*)d_in[3];  const float* b1 = (const float*)d_in[4];
    const float* W2 = (const float*)d_in[5];  const float* b2 = (const float*)d_in[6];
    const float* W3 = (const float*)d_in[7];  const float* b3 = (const float*)d_in[8];
    const float* W4 = (const float*)d_in[9];  const float* b4 = (const float*)d_in[10];
    float* out = (float*)d_out;

    __half *ln, *h1, *h2, *h3, *w1, *w2, *w3, *w4;
    cudaGetSymbolAddress((void**)&ln, g_ln);
    cudaGetSymbolAddress((void**)&h1, g_h1);
    cudaGetSymbolAddress((void**)&h2, g_h2);
    cudaGetSymbolAddress((void**)&h3, g_h3);
    cudaGetSymbolAddress((void**)&w1, g_w1);
    cudaGetSymbolAddress((void**)&w2, g_w2);
    cudaGetSymbolAddress((void**)&w3, g_w3);
    cudaGetSymbolAddress((void**)&w4, g_w4);

    cudaFuncSetAttribute(hgemm<0>, cudaFuncAttributeMaxDynamicSharedMemorySize, SMEM_TOTAL);
    cudaFuncSetAttribute(hgemm<1>, cudaFuncAttributeMaxDynamicSharedMemorySize, SMEM_TOTAL);

    wprep_all<<<(1179648 + 255) / 256, 256>>>(W1, W2, W3, W4, w1, w2, w3, w4);

    ln_kernel<<<TOKENS / 8, 256>>>(x, gamma, beta, ln);

    hgemm<0><<<dim3(HMID / 128, TOKENS / 128), 256, SMEM_TOTAL>>>(
        ln, w1, b1, nullptr, h1, nullptr, HMID, DIM);
    hgemm<0><<<dim3(HMID / 128, TOKENS / 128), 256, SMEM_TOTAL>>>(
        h1, w2, b2, nullptr, h2, nullptr, HMID, HMID);
    hgemm<0><<<dim3(HLOW / 128, TOKENS / 128), 256, SMEM_TOTAL>>>(
        h2, w3, b3, nullptr, h3, nullptr, HLOW, HMID);
    hgemm<1><<<dim3(DIM / 128, TOKENS / 128), 256, SMEM_TOTAL>>>(
        h3, w4, b4, x, nullptr, out, DIM, HLOW);
}

// round 6
// speedup vs baseline: 5.2427x; 1.1097x over previous
#include <cuda_runtime.h>
#include <cuda_fp16.h>
#include <math.h>
#include <cstdint>

#define TOKENS (4*8192)
#define DIM 1024
#define HMID 512
#define HLOW 256

// ---------------------------------------------------------------------------
// Scratch (device globals; no allocation anywhere)
// ---------------------------------------------------------------------------
__device__ __half g_ln[(size_t)TOKENS * DIM];   // 64 MB
__device__ __half g_h1[(size_t)TOKENS * HMID];  // 32 MB
__device__ __half g_h2[(size_t)TOKENS * HMID];  // 32 MB
__device__ __half g_h3[(size_t)TOKENS * HLOW];  // 16 MB
// Transposed fp16 weights: Wt[n*K + k]
__device__ __half g_w1[(size_t)HMID * DIM];
__device__ __half g_w2[(size_t)HMID * HMID];
__device__ __half g_w3[(size_t)HLOW * HMID];
__device__ __half g_w4[(size_t)DIM * HLOW];

// ---------------------------------------------------------------------------
// Helpers (base-target PTX only: sm_80-era features)
// ---------------------------------------------------------------------------
__device__ __forceinline__ uint32_t smem_u32(const void* p) {
    uint32_t a;
    asm("{ .reg .u64 t; cvta.to.shared.u64 t, %1; cvt.u32.u64 %0, t; }"
        : "=r"(a) : "l"(p));
    return a;
}
#define SW128(bo) ((bo) ^ (((bo) >> 3) & 0x70))

#define CP_ASYNC16(dst, src) \
    asm volatile("cp.async.cg.shared.global [%0], [%1], 16;" \
                 :: "r"(dst), "l"(src))
#define CP_COMMIT() asm volatile("cp.async.commit_group;" ::: "memory")
#define CP_WAIT(n)  asm volatile("cp.async.wait_group %0;" :: "n"(n) : "memory")

#define LDMATRIX_X4(r0, r1, r2, r3, a) \
    asm volatile("ldmatrix.sync.aligned.m8n8.x4.shared.b16 {%0,%1,%2,%3}, [%4];" \
                 : "=r"(r0), "=r"(r1), "=r"(r2), "=r"(r3) : "r"(a))

#define MMA16816(c0, c1, c2, c3, a0, a1, a2, a3, b0, b1) \
    asm volatile("mma.sync.aligned.m16n8k16.row.col.f32.f16.f16.f32 " \
                 "{%0,%1,%2,%3}, {%4,%5,%6,%7}, {%8,%9}, {%0,%1,%2,%3};" \
                 : "+f"(c0), "+f"(c1), "+f"(c2), "+f"(c3) \
                 : "r"(a0), "r"(a1), "r"(a2), "r"(a3), "r"(b0), "r"(b1))

__device__ __forceinline__ float gelu_exact(float v) {
    return 0.5f * v * (1.0f + erff(v * 0.70710678118654752f));
}

// ---------------------------------------------------------------------------
// Fused weight prep: all 4 weights, W[K,N] fp32 -> Wt[N,K] fp16, one launch
// ---------------------------------------------------------------------------
__global__ void wprep_all(const float* __restrict__ W1, const float* __restrict__ W2,
                          const float* __restrict__ W3, const float* __restrict__ W4,
                          __half* __restrict__ T1, __half* __restrict__ T2,
                          __half* __restrict__ T3, __half* __restrict__ T4)
{
    int idx = blockIdx.x * blockDim.x + threadIdx.x;
    const float* W; __half* T; int K; int base;
    if (idx < 524288)        { W = W1; T = T1; K = DIM;  base = 0;        }
    else if (idx < 786432)   { W = W2; T = T2; K = HMID; base = 524288;   }
    else if (idx < 917504)   { W = W3; T = T3; K = HMID; base = 786432;   }
    else if (idx < 1179648)  { W = W4; T = T4; K = HLOW; base = 917504;   }
    else return;
    int i = idx - base;
    int n = i / K, k = i - n * K;
    int N = (idx < 524288) ? HMID : (idx < 786432) ? HMID : (idx < 917504) ? HLOW : DIM;
    T[i] = __float2half_rn(W[(size_t)k * N + n]);
}

// ---------------------------------------------------------------------------
// LayerNorm, warp-per-row (no smem, no block barrier): 8 rows / 256-thr block
// ---------------------------------------------------------------------------
__global__ __launch_bounds__(256) void ln_kernel(
    const float* __restrict__ x, const float* __restrict__ gamma,
    const float* __restrict__ beta, __half* __restrict__ y)
{
    const int warp = threadIdx.x >> 5, lane = threadIdx.x & 31;
    const int row = blockIdx.x * 8 + warp;
    const float* xr = x + (size_t)row * DIM;

    float4 v[8];
    float s = 0.0f, q = 0.0f;
    #pragma unroll
    for (int j = 0; j < 8; j++) {
        v[j] = reinterpret_cast<const float4*>(xr)[j * 32 + lane];
        s += v[j].x + v[j].y + v[j].z + v[j].w;
        q += v[j].x*v[j].x + v[j].y*v[j].y + v[j].z*v[j].z + v[j].w*v[j].w;
    }
    #pragma unroll
    for (int o = 16; o > 0; o >>= 1) {
        s += __shfl_xor_sync(~0u, s, o);
        q += __shfl_xor_sync(~0u, q, o);
    }
    const float mu = s * (1.0f / DIM);
    const float var = q * (1.0f / DIM) - mu * mu;
    const float rs = rsqrtf(var + 1e-5f);

    __half* yr = y + (size_t)row * DIM;
    #pragma unroll
    for (int j = 0; j < 8; j++) {
        float4 g = reinterpret_cast<const float4*>(gamma)[j * 32 + lane];
        float4 b = reinterpret_cast<const float4*>(beta)[j * 32 + lane];
        __half2 h0 = __halves2half2(__float2half_rn((v[j].x - mu) * rs * g.x + b.x),
                                    __float2half_rn((v[j].y - mu) * rs * g.y + b.y));
        __half2 h1 = __halves2half2(__float2half_rn((v[j].z - mu) * rs * g.z + b.z),
                                    __float2half_rn((v[j].w - mu) * rs * g.w + b.w));
        uint2 pack = { *reinterpret_cast<uint32_t*>(&h0), *reinterpret_cast<uint32_t*>(&h1) };
        *reinterpret_cast<uint2*>(yr + (size_t)(j * 32 + lane) * 4) = pack;
    }
}

// ---------------------------------------------------------------------------
// fp16 tensor-core GEMM, compile-time K/N: C[128x128] = A[M,K] @ Wt[N,K]^T
// 8 warps (4x2), warp tile 32x64, BK=64, 3-stage cp.async, 1 sync/iter,
// chunk loop FULLY UNROLLED (constant swizzled offsets, constant strides).
// MODE 0: Oh = fp16(gelu(acc+bias));  MODE 1: Of = acc+bias+res (fp32)
// ---------------------------------------------------------------------------
#define STAGE_BYTES 32768          // A 16KB + B 16KB per stage
#define NSTAGE 3
#define SMEM_TOTAL  (NSTAGE * STAGE_BYTES)

template<int MODE, int KDIM, int NDIM>
__global__ __launch_bounds__(256, 2) void hgemm(
    const __half* __restrict__ A, const __half* __restrict__ Bw,
    const float* __restrict__ bias, const float* __restrict__ res,
    __half* __restrict__ Oh, float* __restrict__ Of)
{
    constexpr int NCH = KDIM >> 6;
    extern __shared__ char smem[];
    const uint32_t sb = smem_u32(smem);
    const int tid = threadIdx.x, lid = tid & 31, wid = tid >> 5;
    const int m0 = blockIdx.y * 128, n0 = blockIdx.x * 128;
    const int wm = (wid & 3) * 32;       // warp M offset
    const int wn = (wid >> 2) * 64;      // warp N offset

    float acc[2][8][4];
    #pragma unroll
    for (int i = 0; i < 2; i++)
        #pragma unroll
        for (int j = 0; j < 8; j++)
            #pragma unroll
            for (int k = 0; k < 4; k++) acc[i][j][k] = 0.0f;

    // per-thread load coords (fixed); global pointers advance by constant 64
    const int lr = tid >> 3, lch = tid & 7;
    const __half* Ab = A + (size_t)(m0 + lr) * KDIM + lch * 8;
    const __half* Bb = Bw + (size_t)(n0 + lr) * KDIM + lch * 8;
    // swizzled smem offsets are per-thread constants
    const uint32_t sdo = SW128((uint32_t)(lr * 128 + lch * 16));

    auto load_stage = [&](int s, int c) {
        const uint32_t base = sb + s * STAGE_BYTES + sdo;
        const __half* a = Ab + c * 64;
        const __half* b = Bb + c * 64;
        #pragma unroll
        for (int i = 0; i < 4; i++)
            CP_ASYNC16(base + i * 4096, a + (size_t)(i * 32) * KDIM);
        #pragma unroll
        for (int i = 0; i < 4; i++)
            CP_ASYNC16(base + 16384 + i * 4096, b + (size_t)(i * 32) * KDIM);
        CP_COMMIT();
    };

    load_stage(0, 0);
    load_stage(1, 1);

    // ldmatrix lane address components (per-thread constants)
    const int lrow = (lid & 7) + ((lid >> 3) & 1) * 8;
    const int lkb  = (lid >> 4) * 16;

    #pragma unroll
    for (int c = 0; c < NCH; ++c) {
        CP_WAIT(1);
        __syncthreads();
        if (c + 2 < NCH) load_stage((c + 2) % NSTAGE, c + 2);
        else CP_COMMIT();            // empty group keeps CP_WAIT(1) exact

        const uint32_t abase = sb + (c % NSTAGE) * STAGE_BYTES;
        const uint32_t bbase = abase + 16384;

        #pragma unroll
        for (int kk = 0; kk < 4; ++kk) {
            uint32_t a[2][4], b[8][2];
            #pragma unroll
            for (int mt = 0; mt < 2; ++mt) {
                uint32_t bo = (uint32_t)((wm + mt * 16 + lrow) * 128 + kk * 32 + lkb);
                LDMATRIX_X4(a[mt][0], a[mt][1], a[mt][2], a[mt][3], abase + SW128(bo));
            }
            #pragma unroll
            for (int jp = 0; jp < 4; ++jp) {
                uint32_t r0, r1, r2, r3;
                uint32_t bo = (uint32_t)((wn + jp * 16 + lrow) * 128 + kk * 32 + lkb);
                LDMATRIX_X4(r0, r1, r2, r3, bbase + SW128(bo));
                b[jp * 2][0] = r0; b[jp * 2 + 1][0] = r1;
                b[jp * 2][1] = r2; b[jp * 2 + 1][1] = r3;
            }
            #pragma unroll
            for (int mt = 0; mt < 2; ++mt)
                #pragma unroll
                for (int nt = 0; nt < 8; ++nt)
                    MMA16816(acc[mt][nt][0], acc[mt][nt][1],
                             acc[mt][nt][2], acc[mt][nt][3],
                             a[mt][0], a[mt][1], a[mt][2], a[mt][3],
                             b[nt][0], b[nt][1]);
        }
    }

    // --- epilogue ---
    const int mrow = m0 + wm + (lid >> 2);
    const int ncb  = n0 + wn + (lid & 3) * 2;
    #pragma unroll
    for (int mt = 0; mt < 2; ++mt) {
        const int r0 = mrow + mt * 16;
        #pragma unroll
        for (int nt = 0; nt < 8; ++nt) {
            const int n = ncb + nt * 8;
            float2 bv = *reinterpret_cast<const float2*>(bias + n);
            if (MODE == 0) {
                float v0 = gelu_exact(acc[mt][nt][0] + bv.x);
                float v1 = gelu_exact(acc[mt][nt][1] + bv.y);
                float v2 = gelu_exact(acc[mt][nt][2] + bv.x);
                float v3 = gelu_exact(acc[mt][nt][3] + bv.y);
                __half2 p0 = __halves2half2(__float2half_rn(v0), __float2half_rn(v1));
                __half2 p1 = __halves2half2(__float2half_rn(v2), __float2half_rn(v3));
                *reinterpret_cast<__half2*>(Oh + (size_t)r0 * NDIM + n) = p0;
                *reinterpret_cast<__half2*>(Oh + (size_t)(r0 + 8) * NDIM + n) = p1;
            } else {
                float2 ra = *reinterpret_cast<const float2*>(res + (size_t)r0 * NDIM + n);
                float2 rb = *reinterpret_cast<const float2*>(res + (size_t)(r0 + 8) * NDIM + n);
                float2 o0 = { acc[mt][nt][0] + bv.x + ra.x, acc[mt][nt][1] + bv.y + ra.y };
                float2 o1 = { acc[mt][nt][2] + bv.x + rb.x, acc[mt][nt][3] + bv.y + rb.y };
                *reinterpret_cast<float2*>(Of + (size_t)r0 * NDIM + n) = o0;
                *reinterpret_cast<float2*>(Of + (size_t)(r0 + 8) * NDIM + n) = o1;
            }
        }
    }
}

// ---------------------------------------------------------------------------
extern "C" void kernel_launch(void* const* d_in, const int* in_sizes, int n_in,
                              void* d_out, int out_size)
{
    const float* x     = (const float*)d_in[0];
    const float* gamma = (const float*)d_in[1];
    const float* beta  = (const float*)d_in[2];
    const float* W1 = (const float*)d_in[3];  const float* b1 = (const float*)d_in[4];
    const float* W2 = (const float*)d_in[5];  const float* b2 = (const float*)d_in[6];
    const float* W3 = (const float*)d_in[7];  const float* b3 = (const float*)d_in[8];
    const float* W4 = (const float*)d_in[9];  const float* b4 = (const float*)d_in[10];
    float* out = (float*)d_out;

    __half *ln, *h1, *h2, *h3, *w1, *w2, *w3, *w4;
    cudaGetSymbolAddress((void**)&ln, g_ln);
    cudaGetSymbolAddress((void**)&h1, g_h1);
    cudaGetSymbolAddress((void**)&h2, g_h2);
    cudaGetSymbolAddress((void**)&h3, g_h3);
    cudaGetSymbolAddress((void**)&w1, g_w1);
    cudaGetSymbolAddress((void**)&w2, g_w2);
    cudaGetSymbolAddress((void**)&w3, g_w3);
    cudaGetSymbolAddress((void**)&w4, g_w4);

    cudaFuncSetAttribute(hgemm<0, DIM,  HMID>, cudaFuncAttributeMaxDynamicSharedMemorySize, SMEM_TOTAL);
    cudaFuncSetAttribute(hgemm<0, HMID, HMID>, cudaFuncAttributeMaxDynamicSharedMemorySize, SMEM_TOTAL);
    cudaFuncSetAttribute(hgemm<0, HMID, HLOW>, cudaFuncAttributeMaxDynamicSharedMemorySize, SMEM_TOTAL);
    cudaFuncSetAttribute(hgemm<1, HLOW, DIM>,  cudaFuncAttributeMaxDynamicSharedMemorySize, SMEM_TOTAL);

    wprep_all<<<(1179648 + 255) / 256, 256>>>(W1, W2, W3, W4, w1, w2, w3, w4);

    ln_kernel<<<TOKENS / 8, 256>>>(x, gamma, beta, ln);

    hgemm<0, DIM,  HMID><<<dim3(HMID / 128, TOKENS / 128), 256, SMEM_TOTAL>>>(
        ln, w1, b1, nullptr, h1, nullptr);
    hgemm<0, HMID, HMID><<<dim3(HMID / 128, TOKENS / 128), 256, SMEM_TOTAL>>>(
        h1, w2, b2, nullptr, h2, nullptr);
    hgemm<0, HMID, HLOW><<<dim3(HLOW / 128, TOKENS / 128), 256, SMEM_TOTAL>>>(
        h2, w3, b3, nullptr, h3, nullptr);
    hgemm<1, HLOW, DIM><<<dim3(DIM / 128, TOKENS / 128), 256, SMEM_TOTAL>>>(
        h3, w4, b4, x, nullptr, out);
}